// round 3
// baseline (speedup 1.0000x reference)
#include <cuda_runtime.h>

// ---------------------------------------------------------------------------
// BoxCrossCategoryLoss, round 3.
//  - log2-domain math, fused NEG-recipe log1mexp (unchanged algebra from R0)
//  - f32x2 packed arithmetic: the two independent elements covered by each
//    float4 load ride the lo/hi halves of add/mul/fma.rn.f32x2 (sm_103a
//    double-pumped FP32). sub synthesized via fma(b,-1,a); relu stays scalar
//    FMNMX on the alu pipe. Cuts fma-pipe instruction stream ~1.6x.
//  - final reduction folded into the main kernel (last-block pattern),
//    removing the second launch (~7 us).
// ---------------------------------------------------------------------------

#define GRID_BLOCKS 1184   // 8 * 148 SMs
#define NTHREADS 256

__device__ float        g_partials[GRID_BLOCKS];
__device__ unsigned int g_ctr = 0;

typedef unsigned long long pf2;   // carrier for a packed f32x2 value

__device__ __forceinline__ pf2 PK2(float lo, float hi) {
    pf2 r; asm("mov.b64 %0, {%1, %2};" : "=l"(r) : "f"(lo), "f"(hi)); return r;
}
__device__ __forceinline__ float2 UPK2(pf2 a) {
    float2 r; asm("mov.b64 {%0, %1}, %2;" : "=f"(r.x), "=f"(r.y) : "l"(a)); return r;
}
__device__ __forceinline__ pf2 padd(pf2 a, pf2 b) {
    pf2 r; asm("add.rn.f32x2 %0, %1, %2;" : "=l"(r) : "l"(a), "l"(b)); return r;
}
__device__ __forceinline__ pf2 pmul(pf2 a, pf2 b) {
    pf2 r; asm("mul.rn.f32x2 %0, %1, %2;" : "=l"(r) : "l"(a), "l"(b)); return r;
}
__device__ __forceinline__ pf2 pfma(pf2 a, pf2 b, pf2 c) {
    pf2 r; asm("fma.rn.f32x2 %0, %1, %2, %3;" : "=l"(r) : "l"(a), "l"(b), "l"(c)); return r;
}
// a - b  ==  fma(b, -1, a)   (exact; avoids relying on sub.f32x2)
__device__ __forceinline__ pf2 psub(pf2 a, pf2 b, pf2 NEG1) {
    return pfma(b, NEG1, a);
}

__device__ __forceinline__ float ex2f_(float x) {
    float r; asm("ex2.approx.f32 %0, %1;" : "=f"(r) : "f"(x)); return r;
}
__device__ __forceinline__ float lg2f_(float x) {
    float r; asm("lg2.approx.f32 %0, %1;" : "=f"(r) : "f"(x)); return r;
}
__device__ __forceinline__ pf2 pex2(pf2 a) {
    float2 t = UPK2(a); return PK2(ex2f_(t.x), ex2f_(t.y));
}
__device__ __forceinline__ pf2 plg2(pf2 a) {
    float2 t = UPK2(a); return PK2(lg2f_(t.x), lg2f_(t.y));
}
// log2(1 - 2^x) for x < 0, packed
__device__ __forceinline__ pf2 pl1m2(pf2 a, pf2 ONE, pf2 NEG1) {
    return plg2(psub(ONE, pex2(a), NEG1));
}

__global__ void __launch_bounds__(NTHREADS)
loss_kernel(const float* __restrict__ AB, const float* __restrict__ BA,
            const float* __restrict__ BC, const float* __restrict__ CB,
            const float* __restrict__ AC, const float* __restrict__ CA,
            int n_elems, float* __restrict__ out)
{
    constexpr float Kf = 1.44269504088896340736f;  // log2(e)
    const pf2 ONE  = PK2(1.0f, 1.0f);
    const pf2 NEG1 = PK2(-1.0f, -1.0f);
    const pf2 KK   = PK2(Kf, Kf);

    const float4* AB4 = (const float4*)AB;
    const float4* BA4 = (const float4*)BA;
    const float4* BC4 = (const float4*)BC;
    const float4* CB4 = (const float4*)CB;
    const float4* AC4 = (const float4*)AC;
    const float4* CA4 = (const float4*)CA;

    int n4 = n_elems >> 1;            // one float4 set covers 2 elements
    float accl = 0.0f, acch = 0.0f;   // scalar relu accumulators (lo/hi lanes)

    for (int j = blockIdx.x * NTHREADS + threadIdx.x; j < n4;
         j += GRID_BLOCKS * NTHREADS) {
        float4 vab = AB4[j], vba = BA4[j];
        float4 vbc = BC4[j], vcb = CB4[j];
        float4 vac = AC4[j], vca = CA4[j];

        // pack (elem_i, elem_{i+1}) per column, scale to log2 units
        pf2 ab0 = pmul(PK2(vab.x, vab.z), KK), ab1 = pmul(PK2(vab.y, vab.w), KK);
        pf2 ba0 = pmul(PK2(vba.x, vba.z), KK), ba1 = pmul(PK2(vba.y, vba.w), KK);
        pf2 bc0 = pmul(PK2(vbc.x, vbc.z), KK), bc1 = pmul(PK2(vbc.y, vbc.w), KK);
        pf2 cb0 = pmul(PK2(vcb.x, vcb.z), KK), cb1 = pmul(PK2(vcb.y, vcb.w), KK);
        pf2 ac0 = pmul(PK2(vac.x, vac.z), KK), ac1 = pmul(PK2(vac.y, vac.w), KK);
        pf2 ca0 = pmul(PK2(vca.x, vca.z), KK), ca1 = pmul(PK2(vca.y, vca.w), KK);

        // --- AB pair ---
        pf2 ABla0 = pl1m2(ab0, ONE, NEG1), ABlb0 = pl1m2(ba0, ONE, NEG1);
        pf2 ABla1 = pl1m2(ab1, ONE, NEG1), ABlb1 = pl1m2(ba1, ONE, NEG1);
        pf2 AB0c0 = padd(ab0, ABlb0);
        pf2 AB1c0 = padd(ABla0, ba0);
        pf2 AB2c0 = padd(ab0, ba0);
        pf2 AB0c1 = padd(ab1, ABlb1);
        pf2 AB1c1 = padd(ABla1, ba1);
        pf2 AB2c1 = padd(ab1, ba1);
        pf2 AB3c1 = padd(ABla1, ABlb1);

        // --- BC pair ---
        pf2 BCla0 = pl1m2(bc0, ONE, NEG1), BClb0 = pl1m2(cb0, ONE, NEG1);
        pf2 BCla1 = pl1m2(bc1, ONE, NEG1), BClb1 = pl1m2(cb1, ONE, NEG1);
        pf2 BC0c0 = padd(bc0, BClb0);
        pf2 BC1c0 = padd(BCla0, cb0);
        pf2 BC2c0 = padd(bc0, cb0);
        pf2 BC0c1 = padd(bc1, BClb1);
        pf2 BC1c1 = padd(BCla1, cb1);
        pf2 BC2c1 = padd(bc1, cb1);
        pf2 BC3c1 = padd(BCla1, BClb1);

        // --- AC col1 (direct subtrahends) ---
        pf2 ACla1 = pl1m2(ac1, ONE, NEG1), AClb1 = pl1m2(ca1, ONE, NEG1);
        pf2 AC0 = padd(ac1, AClb1);
        pf2 AC1 = padd(ACla1, ca1);
        pf2 AC2 = padd(ac1, ca1);
        pf2 AC3 = padd(ACla1, AClb1);

        // --- AC col0: fused log1mexp(pAC[k][:,0]) forms ---
        pf2 ua = pex2(ac0);
        pf2 ub = pex2(ca0);
        pf2 w  = pmul(ua, ub);
        pf2 L0 = plg2(padd(psub(ONE, ua, NEG1), w));  // log2(1 - ua(1-ub))
        pf2 L1 = plg2(padd(psub(ONE, ub, NEG1), w));  // log2(1 - (1-ua)ub)
        pf2 L2 = plg2(psub(ONE, w, NEG1));            // log2(1 - ua*ub)

#define RT(S, X) { float2 t_ = UPK2(psub(S, X, NEG1)); \
                   accl += fmaxf(t_.x, 0.0f); acch += fmaxf(t_.y, 0.0f); }

        pf2 S1  = padd(AB0c0, BC0c1);  RT(S1,  AC0) RT(S1,  L1) RT(S1,  L2)
        pf2 S2  = padd(AB0c0, BC2c1);  RT(S2,  AC0) RT(S2,  L1) RT(S2,  L2)
        pf2 S3  = padd(AB1c0, BC1c1);  RT(S3,  AC1) RT(S3,  L0) RT(S3,  L2)
        pf2 S4  = padd(AB1c0, BC2c1);  RT(S4,  AC1) RT(S4,  L0) RT(S4,  L2)
        pf2 S5  = padd(AB2c0, BC0c1);  RT(S5,  AC0) RT(S5,  L1) RT(S5,  L2)
        pf2 S6  = padd(AB2c0, BC1c1);  RT(S6,  AC1) RT(S6,  L0) RT(S6,  L2)
        pf2 S7  = padd(AB2c0, BC2c1);  RT(S7,  AC2)
        pf2 S8  = padd(AB2c0, BC3c1);  RT(S8,  AC3) RT(S8,  L2)
        pf2 S9  = padd(AB0c1, BC0c0);  RT(S9,  AC0) RT(S9,  L1) RT(S9,  L2)
        pf2 S10 = padd(AB0c1, BC2c0);  RT(S10, AC0) RT(S10, L1) RT(S10, L2)
        pf2 S11 = padd(AB1c1, BC1c0);  RT(S11, AC1) RT(S11, L0) RT(S11, L2)
        pf2 S12 = padd(AB1c1, BC2c0);  RT(S12, AC1) RT(S12, L0) RT(S12, L2)
        pf2 S13 = padd(AB2c1, BC2c0);  RT(S13, AC2)
        pf2 S14 = padd(AB3c1, BC2c0);  RT(S14, AC3) RT(S14, L2)
#undef RT
    }

    float acc = accl + acch;

    // warp + block reduction (fixed order -> deterministic)
    #pragma unroll
    for (int o = 16; o > 0; o >>= 1)
        acc += __shfl_xor_sync(0xFFFFFFFFu, acc, o);

    __shared__ float ws[NTHREADS / 32];
    __shared__ bool  amLast;
    if ((threadIdx.x & 31) == 0) ws[threadIdx.x >> 5] = acc;
    __syncthreads();
    if (threadIdx.x == 0) {
        float s = 0.0f;
        #pragma unroll
        for (int i = 0; i < NTHREADS / 32; i++) s += ws[i];
        g_partials[blockIdx.x] = s;
        __threadfence();
        unsigned old = atomicInc(&g_ctr, GRID_BLOCKS - 1);  // wraps to 0: self-reset
        amLast = (old == GRID_BLOCKS - 1);
    }
    __syncthreads();

    if (amLast) {
        __shared__ double sh[NTHREADS];
        double s = 0.0;
        for (int i = threadIdx.x; i < GRID_BLOCKS; i += NTHREADS)
            s += (double)__ldcg(&g_partials[i]);
        sh[threadIdx.x] = s;
        __syncthreads();
        #pragma unroll
        for (int st = NTHREADS / 2; st > 0; st >>= 1) {
            if (threadIdx.x < st) sh[threadIdx.x] += sh[threadIdx.x + st];
            __syncthreads();
        }
        if (threadIdx.x == 0)
            out[0] = (float)(sh[0] * 0.69314718055994530942);  // log2 -> nat
    }
}

extern "C" void kernel_launch(void* const* d_in, const int* in_sizes, int n_in,
                              void* d_out, int out_size)
{
    const float* AB = (const float*)d_in[0];
    const float* BA = (const float*)d_in[1];
    const float* BC = (const float*)d_in[2];
    const float* CB = (const float*)d_in[3];
    const float* AC = (const float*)d_in[4];
    const float* CA = (const float*)d_in[5];
    // d_in[6..8] (xy/yz/xz rel_id) are dead inputs in the reference.

    int n_elems = in_sizes[0] / 2;

    loss_kernel<<<GRID_BLOCKS, NTHREADS>>>(AB, BA, BC, CB, AC, CA, n_elems,
                                           (float*)d_out);
}

// round 5
// speedup vs baseline: 1.0452x; 1.0452x over previous
#include <cuda_runtime.h>

// ---------------------------------------------------------------------------
// BoxCrossCategoryLoss, round 4: hybrid (col0,col1)-packed front end.
// Pairs are the two columns of ONE element -> adjacent regs from float4
// loads -> zero-MOV f32x2 packing. Cross-lane S/RT stage stays scalar.
// Fused last-block reduction (no second launch). 4 relu accumulators.
// ---------------------------------------------------------------------------

#define GRID_BLOCKS 1184   // 8 * 148 SMs
#define NTHREADS 256

__device__ float        g_partials[GRID_BLOCKS];
__device__ unsigned int g_ctr = 0;

typedef unsigned long long pf2;

__device__ __forceinline__ pf2 PK2(float lo, float hi) {
    pf2 r; asm("mov.b64 %0, {%1, %2};" : "=l"(r) : "f"(lo), "f"(hi)); return r;
}
__device__ __forceinline__ float2 UPK2(pf2 a) {
    float2 r; asm("mov.b64 {%0, %1}, %2;" : "=f"(r.x), "=f"(r.y) : "l"(a)); return r;
}
__device__ __forceinline__ pf2 padd(pf2 a, pf2 b) {
    pf2 r; asm("add.rn.f32x2 %0, %1, %2;" : "=l"(r) : "l"(a), "l"(b)); return r;
}
__device__ __forceinline__ pf2 pmul(pf2 a, pf2 b) {
    pf2 r; asm("mul.rn.f32x2 %0, %1, %2;" : "=l"(r) : "l"(a), "l"(b)); return r;
}
__device__ __forceinline__ pf2 pfma(pf2 a, pf2 b, pf2 c) {
    pf2 r; asm("fma.rn.f32x2 %0, %1, %2, %3;" : "=l"(r) : "l"(a), "l"(b), "l"(c)); return r;
}
__device__ __forceinline__ float ex2f_(float x) {
    float r; asm("ex2.approx.f32 %0, %1;" : "=f"(r) : "f"(x)); return r;
}
__device__ __forceinline__ float lg2f_(float x) {
    float r; asm("lg2.approx.f32 %0, %1;" : "=f"(r) : "f"(x)); return r;
}
__device__ __forceinline__ pf2 pex2(pf2 a) {
    float2 t = UPK2(a); return PK2(ex2f_(t.x), ex2f_(t.y));
}
__device__ __forceinline__ pf2 plg2(pf2 a) {
    float2 t = UPK2(a); return PK2(lg2f_(t.x), lg2f_(t.y));
}

// One element: packed inputs p** = (col0, col1), already scaled to log2 units.
__device__ __forceinline__ void elem_loss(
    pf2 pab, pf2 pba, pf2 pbc, pf2 pcb, pf2 pac, pf2 pca,
    pf2 ONE, pf2 NEG1,
    float& a0, float& a1, float& a2, float& a3)
{
    // packed 1 - 2^x for the four AB/BC inputs (both columns at once)
    pf2 s_ab = pfma(pex2(pab), NEG1, ONE);
    pf2 s_ba = pfma(pex2(pba), NEG1, ONE);
    pf2 s_bc = pfma(pex2(pbc), NEG1, ONE);
    pf2 s_cb = pfma(pex2(pcb), NEG1, ONE);
    pf2 Lab = plg2(s_ab), Lba = plg2(s_ba);
    pf2 Lbc = plg2(s_bc), Lcb = plg2(s_cb);

    // packed probability sums (PC, CP, CR) for AB and BC
    pf2 pAB0 = padd(pab, Lba);
    pf2 pAB1 = padd(Lab, pba);
    pf2 pAB2 = padd(pab, pba);
    pf2 pBC0 = padd(pbc, Lcb);
    pf2 pBC1 = padd(Lbc, pcb);
    pf2 pBC2 = padd(pbc, pcb);

    float2 lab = UPK2(Lab), lba = UPK2(Lba);
    float2 lbc = UPK2(Lbc), lcb = UPK2(Lcb);
    float AB3c1 = lab.y + lba.y;     // NR col1
    float BC3c1 = lbc.y + lcb.y;

    // AC: col0 -> fused forms via u's, col1 -> normal log-probs
    pf2 e_ac = pex2(pac), e_ca = pex2(pca);
    pf2 s_ac = pfma(e_ac, NEG1, ONE);   // (1-ua, 1-exp(ac1))
    pf2 s_ca = pfma(e_ca, NEG1, ONE);
    float2 sac = UPK2(s_ac), sca = UPK2(s_ca);
    float2 eac = UPK2(e_ac), eca = UPK2(e_ca);
    float2 vac = UPK2(pac),  vca = UPK2(pca);

    float ACla1 = lg2f_(sac.y), AClb1 = lg2f_(sca.y);
    float AC0 = vac.y + AClb1;
    float AC1 = ACla1 + vca.y;
    float AC2 = vac.y + vca.y;
    float AC3 = ACla1 + AClb1;

    float w  = eac.x * eca.x;
    float L0 = lg2f_(sac.x + w);       // log2(1 - ua(1-ub))
    float L1 = lg2f_(sca.x + w);       // log2(1 - (1-ua)ub)
    float L2 = lg2f_(1.0f - w);        // log2(1 - ua*ub)

    float2 A0 = UPK2(pAB0), A1 = UPK2(pAB1), A2 = UPK2(pAB2);
    float2 B0 = UPK2(pBC0), B1 = UPK2(pBC1), B2 = UPK2(pBC2);

#define RT0(S, X) a0 += fmaxf((S) - (X), 0.0f);
#define RT1(S, X) a1 += fmaxf((S) - (X), 0.0f);
#define RT2(S, X) a2 += fmaxf((S) - (X), 0.0f);
#define RT3(S, X) a3 += fmaxf((S) - (X), 0.0f);

    float S1  = A0.x + B0.y;  RT0(S1,  AC0) RT1(S1,  L1) RT2(S1,  L2)
    float S2  = A0.x + B2.y;  RT3(S2,  AC0) RT0(S2,  L1) RT1(S2,  L2)
    float S3  = A1.x + B1.y;  RT2(S3,  AC1) RT3(S3,  L0) RT0(S3,  L2)
    float S4  = A1.x + B2.y;  RT1(S4,  AC1) RT2(S4,  L0) RT3(S4,  L2)
    float S5  = A2.x + B0.y;  RT0(S5,  AC0) RT1(S5,  L1) RT2(S5,  L2)
    float S6  = A2.x + B1.y;  RT3(S6,  AC1) RT0(S6,  L0) RT1(S6,  L2)
    float S7  = A2.x + B2.y;  RT2(S7,  AC2)
    float S8  = A2.x + BC3c1; RT3(S8,  AC3) RT0(S8,  L2)
    float S9  = A0.y + B0.x;  RT1(S9,  AC0) RT2(S9,  L1) RT3(S9,  L2)
    float S10 = A0.y + B2.x;  RT0(S10, AC0) RT1(S10, L1) RT2(S10, L2)
    float S11 = A1.y + B1.x;  RT3(S11, AC1) RT0(S11, L0) RT1(S11, L2)
    float S12 = A1.y + B2.x;  RT2(S12, AC1) RT3(S12, L0) RT0(S12, L2)
    float S13 = A2.y + B2.x;  RT1(S13, AC2)
    float S14 = AB3c1 + B2.x; RT2(S14, AC3) RT3(S14, L2)
#undef RT0
#undef RT1
#undef RT2
#undef RT3
}

__global__ void __launch_bounds__(NTHREADS)
loss_kernel(const float* __restrict__ AB, const float* __restrict__ BA,
            const float* __restrict__ BC, const float* __restrict__ CB,
            const float* __restrict__ AC, const float* __restrict__ CA,
            int n_elems, float* __restrict__ out)
{
    constexpr float Kf = 1.44269504088896340736f;  // log2(e)
    const pf2 ONE  = PK2(1.0f, 1.0f);
    const pf2 NEG1 = PK2(-1.0f, -1.0f);
    const pf2 KK   = PK2(Kf, Kf);

    const float4* AB4 = (const float4*)AB;
    const float4* BA4 = (const float4*)BA;
    const float4* BC4 = (const float4*)BC;
    const float4* CB4 = (const float4*)CB;
    const float4* AC4 = (const float4*)AC;
    const float4* CA4 = (const float4*)CA;

    int n4 = n_elems >> 1;   // one float4 per array covers 2 elements
    float a0 = 0.0f, a1 = 0.0f, a2 = 0.0f, a3 = 0.0f;

    for (int j = blockIdx.x * NTHREADS + threadIdx.x; j < n4;
         j += GRID_BLOCKS * NTHREADS) {
        float4 vab = AB4[j], vba = BA4[j];
        float4 vbc = BC4[j], vcb = CB4[j];
        float4 vac = AC4[j], vca = CA4[j];

        // element A: (x, y) adjacent -> MOV-free pack; element B: (z, w)
        elem_loss(pmul(PK2(vab.x, vab.y), KK), pmul(PK2(vba.x, vba.y), KK),
                  pmul(PK2(vbc.x, vbc.y), KK), pmul(PK2(vcb.x, vcb.y), KK),
                  pmul(PK2(vac.x, vac.y), KK), pmul(PK2(vca.x, vca.y), KK),
                  ONE, NEG1, a0, a1, a2, a3);
        elem_loss(pmul(PK2(vab.z, vab.w), KK), pmul(PK2(vba.z, vba.w), KK),
                  pmul(PK2(vbc.z, vbc.w), KK), pmul(PK2(vcb.z, vcb.w), KK),
                  pmul(PK2(vac.z, vac.w), KK), pmul(PK2(vca.z, vca.w), KK),
                  ONE, NEG1, a0, a1, a2, a3);
    }

    // odd tail (not hit for N = 8M)
    if ((n_elems & 1) && blockIdx.x == 0 && threadIdx.x == 0) {
        int i = n_elems - 1;
        elem_loss(pmul(PK2(AB[2*i], AB[2*i+1]), KK), pmul(PK2(BA[2*i], BA[2*i+1]), KK),
                  pmul(PK2(BC[2*i], BC[2*i+1]), KK), pmul(PK2(CB[2*i], CB[2*i+1]), KK),
                  pmul(PK2(AC[2*i], AC[2*i+1]), KK), pmul(PK2(CA[2*i], CA[2*i+1]), KK),
                  ONE, NEG1, a0, a1, a2, a3);
    }

    float acc = (a0 + a1) + (a2 + a3);

    #pragma unroll
    for (int o = 16; o > 0; o >>= 1)
        acc += __shfl_xor_sync(0xFFFFFFFFu, acc, o);

    __shared__ float ws[NTHREADS / 32];
    __shared__ bool  amLast;
    if ((threadIdx.x & 31) == 0) ws[threadIdx.x >> 5] = acc;
    __syncthreads();
    if (threadIdx.x == 0) {
        float s = 0.0f;
        #pragma unroll
        for (int i = 0; i < NTHREADS / 32; i++) s += ws[i];
        g_partials[blockIdx.x] = s;
        __threadfence();
        unsigned old = atomicInc(&g_ctr, GRID_BLOCKS - 1);  // wraps to 0
        amLast = (old == GRID_BLOCKS - 1);
    }
    __syncthreads();

    if (amLast) {
        __shared__ double sh[NTHREADS];
        double s = 0.0;
        for (int i = threadIdx.x; i < GRID_BLOCKS; i += NTHREADS)
            s += (double)__ldcg(&g_partials[i]);
        sh[threadIdx.x] = s;
        __syncthreads();
        #pragma unroll
        for (int st = NTHREADS / 2; st > 0; st >>= 1) {
            if (threadIdx.x < st) sh[threadIdx.x] += sh[threadIdx.x + st];
            __syncthreads();
        }
        if (threadIdx.x == 0)
            out[0] = (float)(sh[0] * 0.69314718055994530942);  // log2 -> nat
    }
}

extern "C" void kernel_launch(void* const* d_in, const int* in_sizes, int n_in,
                              void* d_out, int out_size)
{
    const float* AB = (const float*)d_in[0];
    const float* BA = (const float*)d_in[1];
    const float* BC = (const float*)d_in[2];
    const float* CB = (const float*)d_in[3];
    const float* AC = (const float*)d_in[4];
    const float* CA = (const float*)d_in[5];
    // d_in[6..8] (xy/yz/xz rel_id) are dead inputs in the reference.

    int n_elems = in_sizes[0] / 2;

    loss_kernel<<<GRID_BLOCKS, NTHREADS>>>(AB, BA, BC, CB, AC, CA, n_elems,
                                           (float*)d_out);
}